// round 1
// baseline (speedup 1.0000x reference)
#include <cuda_runtime.h>
#include <math.h>

#define NB 4
#define T 72000
#define TS 300
#define NCB 8
#define CBS 1024
#define CBD 64
#define DM 512

// out offsets (floats): a_tokens, b_logits, s1, s2, s3, s4
#define OFF_A  0
#define OFF_BL 9600
#define OFF_S1 316800
#define OFF_S2 316824
#define OFF_S3 317848
#define OFF_S4 319896

__device__ float g_z[NB * TS * DM];      // encoder output z (B,300,512)
__device__ float g_cn[NCB * CBS];        // 0.5*|c|^2 per code

__device__ __forceinline__ float elu1(float x) { return x > 0.f ? x : expm1f(x); }

__device__ __forceinline__ unsigned fordu(float f) {
    unsigned u = __float_as_uint(f);
    return u ^ (unsigned)(((int)u >> 31) | 0x80000000);
}

// ---------------------------------------------------------------------------
// Kernel 0: codebook half-norms
// ---------------------------------------------------------------------------
__global__ void cn_kernel(const float* __restrict__ cb) {
    int i = blockIdx.x * blockDim.x + threadIdx.x;
    if (i < NCB * CBS) {
        const float* c = cb + i * CBD;
        float s = 0.f;
        #pragma unroll
        for (int d = 0; d < CBD; d++) s = fmaf(c[d], c[d], s);
        g_cn[i] = 0.5f * s;
    }
}

// ---------------------------------------------------------------------------
// Kernel 1: fused encoder. One block = one batch x 4 subsample positions.
// Only computes convs inside the 17-sample receptive field of each subsample.
// Block with last group also writes s1..s4 tails.
// ---------------------------------------------------------------------------
#define EP 4
__global__ __launch_bounds__(256) void enc_kernel(
    const float* __restrict__ audio,
    const float* __restrict__ w1c, const float* __restrict__ b1c,
    const float* __restrict__ w2c, const float* __restrict__ b2c,
    const float* __restrict__ w3c, const float* __restrict__ b3c,
    const float* __restrict__ w4c, const float* __restrict__ b4c,
    float* __restrict__ out)
{
    __shared__ float aud[EP * 17];
    __shared__ float c1s[EP * 11 * 64];
    __shared__ float c2s[EP * 7 * 128];
    __shared__ float c3s[EP * 3 * 256];

    const int tid = threadIdx.x;
    const int b = blockIdx.x / 75;
    const int g = blockIdx.x % 75;
    const int tb = g * EP;   // subsample position base (0..296)

    // load audio windows: position p -> t0 = (tb+p)*240+239, need [t0-16, t0]
    for (int idx = tid; idx < EP * 17; idx += 256) {
        int p = idx / 17, u = idx - p * 17;
        int t0 = (tb + p) * 240 + 239;
        aud[idx] = audio[b * T + t0 - 16 + u];
    }
    __syncthreads();

    // conv1 (1->64, K=7) at offsets j=0..10 (t = t0-10+j)
    for (int idx = tid; idx < EP * 11 * 64; idx += 256) {
        int c = idx & 63;
        int r = idx >> 6;
        int p = r / 11, j = r - p * 11;
        float acc = b1c[c];
        #pragma unroll
        for (int k = 0; k < 7; k++) acc = fmaf(w1c[c * 7 + k], aud[p * 17 + j + k], acc);
        c1s[idx] = elu1(acc);
    }
    __syncthreads();

    // conv2 (64->128, K=5) at offsets j=0..6 (t = t0-6+j)
    {
        const int o = tid & 127;
        const int half = tid >> 7;
        float acc[2][7];
        const float bo = b2c[o];
        #pragma unroll
        for (int pp = 0; pp < 2; pp++)
            #pragma unroll
            for (int j = 0; j < 7; j++) acc[pp][j] = bo;
        const float* w = w2c + o * 64 * 5;
        for (int i = 0; i < 64; i++) {
            float wv[5];
            #pragma unroll
            for (int k = 0; k < 5; k++) wv[k] = w[i * 5 + k];
            #pragma unroll
            for (int pp = 0; pp < 2; pp++) {
                int p = half * 2 + pp;
                float s[11];
                #pragma unroll
                for (int ji = 0; ji < 11; ji++) s[ji] = c1s[(p * 11 + ji) * 64 + i];
                #pragma unroll
                for (int j = 0; j < 7; j++)
                    #pragma unroll
                    for (int k = 0; k < 5; k++)
                        acc[pp][j] = fmaf(wv[k], s[j + k], acc[pp][j]);
            }
        }
        #pragma unroll
        for (int pp = 0; pp < 2; pp++) {
            int p = half * 2 + pp;
            #pragma unroll
            for (int j = 0; j < 7; j++)
                c2s[(p * 7 + j) * 128 + o] = elu1(acc[pp][j]);
        }
    }
    __syncthreads();

    // conv3 (128->256, K=5) at offsets j=0..2 (t = t0-2+j)
    {
        const int o = tid;
        float acc[EP][3];
        const float bo = b3c[o];
        #pragma unroll
        for (int p = 0; p < EP; p++)
            #pragma unroll
            for (int j = 0; j < 3; j++) acc[p][j] = bo;
        const float* w = w3c + o * 128 * 5;
        for (int i = 0; i < 128; i++) {
            float wv[5];
            #pragma unroll
            for (int k = 0; k < 5; k++) wv[k] = w[i * 5 + k];
            #pragma unroll
            for (int p = 0; p < EP; p++) {
                float s[7];
                #pragma unroll
                for (int ji = 0; ji < 7; ji++) s[ji] = c2s[(p * 7 + ji) * 128 + i];
                #pragma unroll
                for (int j = 0; j < 3; j++)
                    #pragma unroll
                    for (int k = 0; k < 5; k++)
                        acc[p][j] = fmaf(wv[k], s[j + k], acc[p][j]);
            }
        }
        #pragma unroll
        for (int p = 0; p < EP; p++)
            #pragma unroll
            for (int j = 0; j < 3; j++)
                c3s[(p * 3 + j) * 256 + o] = elu1(acc[p][j]);
    }
    __syncthreads();

    // conv4 (256->512, K=3) at t0 only -> z
    {
        float accA[EP], accB[EP];
        const float bA = b4c[tid], bB = b4c[tid + 256];
        #pragma unroll
        for (int p = 0; p < EP; p++) { accA[p] = bA; accB[p] = bB; }
        const float* wA = w4c + tid * 768;
        const float* wB = w4c + (tid + 256) * 768;
        for (int i = 0; i < 256; i++) {
            float wa0 = wA[i * 3 + 0], wa1 = wA[i * 3 + 1], wa2 = wA[i * 3 + 2];
            float wb0 = wB[i * 3 + 0], wb1 = wB[i * 3 + 1], wb2 = wB[i * 3 + 2];
            #pragma unroll
            for (int p = 0; p < EP; p++) {
                float s0 = c3s[(p * 3 + 0) * 256 + i];
                float s1 = c3s[(p * 3 + 1) * 256 + i];
                float s2 = c3s[(p * 3 + 2) * 256 + i];
                accA[p] = fmaf(wa2, s2, fmaf(wa1, s1, fmaf(wa0, s0, accA[p])));
                accB[p] = fmaf(wb2, s2, fmaf(wb1, s1, fmaf(wb0, s0, accB[p])));
            }
        }
        #pragma unroll
        for (int p = 0; p < EP; p++) {
            int zoff = (b * TS + tb + p) * DM;
            g_z[zoff + tid] = elu1(accA[p]);
            g_z[zoff + tid + 256] = elu1(accB[p]);
        }
    }

    // tails (last group per batch contains t0 = 71999 at p = 3)
    if (g == 74) {
        if (tid < 6) out[OFF_S1 + b * 6 + tid] = audio[b * T + (T - 6) + tid];
        for (int idx = tid; idx < 64 * 4; idx += 256) {
            int c = idx >> 2, u = idx & 3;
            out[OFF_S2 + (b * 64 + c) * 4 + u] = c1s[(3 * 11 + 7 + u) * 64 + c];
        }
        for (int idx = tid; idx < 128 * 4; idx += 256) {
            int c = idx >> 2, u = idx & 3;
            out[OFF_S3 + (b * 128 + c) * 4 + u] = c2s[(3 * 7 + 3 + u) * 128 + c];
        }
        for (int idx = tid; idx < 256 * 2; idx += 256) {
            int c = idx >> 1, u = idx & 1;
            out[OFF_S4 + (b * 256 + c) * 2 + u] = c3s[(3 * 3 + 1 + u) * 256 + c];
        }
    }
}

// ---------------------------------------------------------------------------
// Kernel 2: RVQ (8 sequential codebooks, argmin over 1024 codes) + head GEMM.
// One block = one batch x 10 subsample positions.
// ---------------------------------------------------------------------------
#define RP 10
__global__ __launch_bounds__(256) void rvq_kernel(
    const float* __restrict__ cb,
    const float* __restrict__ hw,
    const float* __restrict__ hb,
    float* __restrict__ out)
{
    __shared__ float zblk[RP * DM];
    __shared__ float zqsh[RP * DM];
    __shared__ float rs[RP * 64];
    __shared__ unsigned long long cand[RP * 8];
    __shared__ unsigned long long bestk[RP];

    const int tid = threadIdx.x;
    const int lane = tid & 31;
    const int wid = tid >> 5;
    const int b = blockIdx.x / 30;
    const int g = blockIdx.x % 30;

    for (int idx = tid; idx < RP * DM; idx += 256) {
        int p = idx >> 9;
        zblk[idx] = g_z[(b * TS + g * RP + p) * DM + (idx & 511)];
    }
    __syncthreads();
    for (int idx = tid; idx < RP * 64; idx += 256) {
        int p = idx >> 6;
        rs[idx] = zblk[p * DM + (idx & 63)];
    }
    __syncthreads();

    for (int i = 0; i < NCB; i++) {
        const float* cbi = cb + i * CBS * CBD;
        // each thread: codes tid, tid+256, tid+512, tid+768 vs all RP residuals
        float dot[4][RP];
        #pragma unroll
        for (int q = 0; q < 4; q++)
            #pragma unroll
            for (int p = 0; p < RP; p++) dot[q][p] = 0.f;
        for (int d = 0; d < CBD; d++) {
            float cv[4];
            #pragma unroll
            for (int q = 0; q < 4; q++) cv[q] = cbi[(tid + q * 256) * CBD + d];
            #pragma unroll
            for (int p = 0; p < RP; p++) {
                float rv = rs[p * 64 + d];
                #pragma unroll
                for (int q = 0; q < 4; q++) dot[q][p] = fmaf(cv[q], rv, dot[q][p]);
            }
        }
        // score = dot - 0.5|c|^2; argmax == argmin(dist); key packs (score, ~code)
        unsigned long long best[RP];
        #pragma unroll
        for (int p = 0; p < RP; p++) best[p] = 0ull;
        #pragma unroll
        for (int q = 0; q < 4; q++) {
            int code = tid + q * 256;
            float cn = g_cn[i * CBS + code];
            unsigned invc = ~(unsigned)code;
            #pragma unroll
            for (int p = 0; p < RP; p++) {
                float sc = dot[q][p] - cn;
                unsigned long long key = (((unsigned long long)fordu(sc)) << 32) | invc;
                if (key > best[p]) best[p] = key;
            }
        }
        #pragma unroll
        for (int off = 16; off > 0; off >>= 1) {
            #pragma unroll
            for (int p = 0; p < RP; p++) {
                unsigned long long other = __shfl_down_sync(0xFFFFFFFFu, best[p], off);
                if (other > best[p]) best[p] = other;
            }
        }
        if (lane == 0) {
            #pragma unroll
            for (int p = 0; p < RP; p++) cand[p * 8 + wid] = best[p];
        }
        __syncthreads();
        if (tid < RP) {
            unsigned long long m = cand[tid * 8];
            #pragma unroll
            for (int w = 1; w < 8; w++) {
                unsigned long long v = cand[tid * 8 + w];
                if (v > m) m = v;
            }
            bestk[tid] = m;
            unsigned code = ~(unsigned)(m & 0xFFFFFFFFull);
            out[OFF_A + (b * NCB + i) * TS + g * RP + tid] = (float)code;
        }
        __syncthreads();
        // write q into z_q, update residual r = z[i+1] + (r - q)
        for (int idx = tid; idx < RP * 64; idx += 256) {
            int p = idx >> 6, d = idx & 63;
            unsigned code = ~(unsigned)(bestk[p] & 0xFFFFFFFFull);
            float qv = cbi[code * CBD + d];
            zqsh[p * DM + i * 64 + d] = qv;
            if (i < NCB - 1)
                rs[idx] = zblk[p * DM + (i + 1) * 64 + d] + rs[idx] - qv;
        }
        __syncthreads();
    }

    // head: b_logits[b,h,t,o] = z_q . head_w[h,o,:] + head_b[h,o]
    {
        float acc[RP];
        #pragma unroll
        for (int p = 0; p < RP; p++) acc[p] = 0.f;
        const float* w = hw + tid * DM;
        for (int d = 0; d < DM; d++) {
            float wv = w[d];
            #pragma unroll
            for (int p = 0; p < RP; p++) acc[p] = fmaf(wv, zqsh[p * DM + d], acc[p]);
        }
        int h = tid >> 6, o = tid & 63;
        float bb = hb[tid];
        #pragma unroll
        for (int p = 0; p < RP; p++)
            out[OFF_BL + ((b * 4 + h) * TS + g * RP + p) * 64 + o] = acc[p] + bb;
    }
}

// ---------------------------------------------------------------------------
extern "C" void kernel_launch(void* const* d_in, const int* in_sizes, int n_in,
                              void* d_out, int out_size)
{
    const float* audio = (const float*)d_in[0];
    const float* w1 = (const float*)d_in[1];
    const float* b1 = (const float*)d_in[2];
    const float* w2 = (const float*)d_in[3];
    const float* b2 = (const float*)d_in[4];
    const float* w3 = (const float*)d_in[5];
    const float* b3 = (const float*)d_in[6];
    const float* w4 = (const float*)d_in[7];
    const float* b4 = (const float*)d_in[8];
    const float* cb = (const float*)d_in[9];
    const float* hw = (const float*)d_in[10];
    const float* hb = (const float*)d_in[11];
    float* out = (float*)d_out;

    cn_kernel<<<(NCB * CBS + 255) / 256, 256>>>(cb);
    enc_kernel<<<NB * 75, 256>>>(audio, w1, b1, w2, b2, w3, b3, w4, b4, out);
    rvq_kernel<<<NB * 30, 256>>>(cb, hw, hb, out);
}

// round 2
// speedup vs baseline: 3.5943x; 3.5943x over previous
#include <cuda_runtime.h>
#include <math.h>

#define NB 4
#define T 72000
#define TS 300
#define NCB 8
#define CBS 1024
#define CBD 64
#define DM 512

// out offsets (floats): a_tokens, b_logits, s1, s2, s3, s4
#define OFF_A  0
#define OFF_BL 9600
#define OFF_S1 316800
#define OFF_S2 316824
#define OFF_S3 317848
#define OFF_S4 319896

__device__ float g_z[NB * TS * DM];      // encoder output z (B,300,512)
__device__ float g_cn[NCB * CBS];        // 0.5*|c|^2 per code
// transposed (coalesced) operands
__device__ float g_w2t[64 * 5 * 128];    // [(i*5+k)][o]
__device__ float g_w3t[128 * 5 * 256];   // [(i*5+k)][o]
__device__ float g_w4t[256 * 3 * 512];   // [(i*3+k)][o]
__device__ float g_hwt[DM * 256];        // [d][h*64+o]
__device__ float g_cbt[NCB * CBD * CBS]; // [i][d][code]

__device__ __forceinline__ float elu1(float x) { return x > 0.f ? x : expm1f(x); }

__device__ __forceinline__ unsigned fordu(float f) {
    unsigned u = __float_as_uint(f);
    return u ^ (unsigned)(((int)u >> 31) | 0x80000000);
}

// ---------------------------------------------------------------------------
// Kernel 0: transpose weights/codebooks into coalesced layouts + code norms
// ---------------------------------------------------------------------------
#define N_W2 40960
#define N_W3 163840
#define N_W4 393216
#define N_HW 131072
#define N_CB 524288
#define N_CN 8192
#define N_PREP (N_W2 + N_W3 + N_W4 + N_HW + N_CB + N_CN)

__global__ void prep_kernel(const float* __restrict__ w2,
                            const float* __restrict__ w3,
                            const float* __restrict__ w4,
                            const float* __restrict__ hw,
                            const float* __restrict__ cb)
{
    int idx = blockIdx.x * blockDim.x + threadIdx.x;
    if (idx < N_W2) {
        int ik = idx >> 7, o = idx & 127;
        g_w2t[idx] = w2[o * 320 + ik];
        return;
    }
    idx -= N_W2;
    if (idx < N_W3) {
        int ik = idx >> 8, o = idx & 255;
        g_w3t[idx] = w3[o * 640 + ik];
        return;
    }
    idx -= N_W3;
    if (idx < N_W4) {
        int ik = idx >> 9, o = idx & 511;
        g_w4t[idx] = w4[o * 768 + ik];
        return;
    }
    idx -= N_W4;
    if (idx < N_HW) {
        int d = idx >> 8, t = idx & 255;
        g_hwt[idx] = hw[t * DM + d];
        return;
    }
    idx -= N_HW;
    if (idx < N_CB) {
        int i = idx >> 16;
        int r = idx & 65535;
        int d = r >> 10, c = r & 1023;
        g_cbt[idx] = cb[(i * CBS + c) * CBD + d];
        return;
    }
    idx -= N_CB;
    if (idx < N_CN) {
        const float* c = cb + idx * CBD;
        float s = 0.f;
        #pragma unroll
        for (int d = 0; d < CBD; d++) s = fmaf(c[d], c[d], s);
        g_cn[idx] = 0.5f * s;
    }
}

// ---------------------------------------------------------------------------
// Kernel 1: fused encoder. One block = one batch x 4 subsample positions.
// Only computes convs inside the 17-sample receptive field of each subsample.
// All weight reads are from transposed, lane-coalesced layouts.
// ---------------------------------------------------------------------------
#define EP 4
__global__ __launch_bounds__(256) void enc_kernel(
    const float* __restrict__ audio,
    const float* __restrict__ w1c, const float* __restrict__ b1c,
    const float* __restrict__ b2c,
    const float* __restrict__ b3c,
    const float* __restrict__ b4c,
    float* __restrict__ out)
{
    __shared__ float aud[EP * 17];
    __shared__ float c1s[EP * 11 * 64];
    __shared__ float c2s[EP * 7 * 128];
    __shared__ float c3s[EP * 3 * 256];

    const int tid = threadIdx.x;
    const int b = blockIdx.x / 75;
    const int g = blockIdx.x % 75;
    const int tb = g * EP;   // subsample position base (0..296)

    // load audio windows: position p -> t0 = (tb+p)*240+239, need [t0-16, t0]
    for (int idx = tid; idx < EP * 17; idx += 256) {
        int p = idx / 17, u = idx - p * 17;
        int t0 = (tb + p) * 240 + 239;
        aud[idx] = audio[b * T + t0 - 16 + u];
    }
    __syncthreads();

    // conv1 (1->64, K=7) at offsets j=0..10 (t = t0-10+j)
    for (int idx = tid; idx < EP * 11 * 64; idx += 256) {
        int c = idx & 63;
        int r = idx >> 6;
        int p = r / 11, j = r - p * 11;
        float acc = b1c[c];
        #pragma unroll
        for (int k = 0; k < 7; k++) acc = fmaf(w1c[c * 7 + k], aud[p * 17 + j + k], acc);
        c1s[idx] = elu1(acc);
    }
    __syncthreads();

    // conv2 (64->128, K=5) at offsets j=0..6 (t = t0-6+j)
    {
        const int o = tid & 127;
        const int half = tid >> 7;
        float acc[2][7];
        const float bo = b2c[o];
        #pragma unroll
        for (int pp = 0; pp < 2; pp++)
            #pragma unroll
            for (int j = 0; j < 7; j++) acc[pp][j] = bo;
        for (int i = 0; i < 64; i++) {
            float wv[5];
            #pragma unroll
            for (int k = 0; k < 5; k++) wv[k] = g_w2t[(i * 5 + k) * 128 + o];
            #pragma unroll
            for (int pp = 0; pp < 2; pp++) {
                int p = half * 2 + pp;
                float s[11];
                #pragma unroll
                for (int ji = 0; ji < 11; ji++) s[ji] = c1s[(p * 11 + ji) * 64 + i];
                #pragma unroll
                for (int j = 0; j < 7; j++)
                    #pragma unroll
                    for (int k = 0; k < 5; k++)
                        acc[pp][j] = fmaf(wv[k], s[j + k], acc[pp][j]);
            }
        }
        #pragma unroll
        for (int pp = 0; pp < 2; pp++) {
            int p = half * 2 + pp;
            #pragma unroll
            for (int j = 0; j < 7; j++)
                c2s[(p * 7 + j) * 128 + o] = elu1(acc[pp][j]);
        }
    }
    __syncthreads();

    // conv3 (128->256, K=5) at offsets j=0..2 (t = t0-2+j)
    {
        const int o = tid;
        float acc[EP][3];
        const float bo = b3c[o];
        #pragma unroll
        for (int p = 0; p < EP; p++)
            #pragma unroll
            for (int j = 0; j < 3; j++) acc[p][j] = bo;
        for (int i = 0; i < 128; i++) {
            float wv[5];
            #pragma unroll
            for (int k = 0; k < 5; k++) wv[k] = g_w3t[(i * 5 + k) * 256 + o];
            #pragma unroll
            for (int p = 0; p < EP; p++) {
                float s[7];
                #pragma unroll
                for (int ji = 0; ji < 7; ji++) s[ji] = c2s[(p * 7 + ji) * 128 + i];
                #pragma unroll
                for (int j = 0; j < 3; j++)
                    #pragma unroll
                    for (int k = 0; k < 5; k++)
                        acc[p][j] = fmaf(wv[k], s[j + k], acc[p][j]);
            }
        }
        #pragma unroll
        for (int p = 0; p < EP; p++)
            #pragma unroll
            for (int j = 0; j < 3; j++)
                c3s[(p * 3 + j) * 256 + o] = elu1(acc[p][j]);
    }
    __syncthreads();

    // conv4 (256->512, K=3) at t0 only -> z
    {
        float accA[EP], accB[EP];
        const float bA = b4c[tid], bB = b4c[tid + 256];
        #pragma unroll
        for (int p = 0; p < EP; p++) { accA[p] = bA; accB[p] = bB; }
        for (int i = 0; i < 256; i++) {
            float wa0 = g_w4t[(i * 3 + 0) * 512 + tid];
            float wa1 = g_w4t[(i * 3 + 1) * 512 + tid];
            float wa2 = g_w4t[(i * 3 + 2) * 512 + tid];
            float wb0 = g_w4t[(i * 3 + 0) * 512 + tid + 256];
            float wb1 = g_w4t[(i * 3 + 1) * 512 + tid + 256];
            float wb2 = g_w4t[(i * 3 + 2) * 512 + tid + 256];
            #pragma unroll
            for (int p = 0; p < EP; p++) {
                float s0 = c3s[(p * 3 + 0) * 256 + i];
                float s1 = c3s[(p * 3 + 1) * 256 + i];
                float s2 = c3s[(p * 3 + 2) * 256 + i];
                accA[p] = fmaf(wa2, s2, fmaf(wa1, s1, fmaf(wa0, s0, accA[p])));
                accB[p] = fmaf(wb2, s2, fmaf(wb1, s1, fmaf(wb0, s0, accB[p])));
            }
        }
        #pragma unroll
        for (int p = 0; p < EP; p++) {
            int zoff = (b * TS + tb + p) * DM;
            g_z[zoff + tid] = elu1(accA[p]);
            g_z[zoff + tid + 256] = elu1(accB[p]);
        }
    }

    // tails (last group per batch contains t0 = 71999 at p = 3)
    if (g == 74) {
        if (tid < 6) out[OFF_S1 + b * 6 + tid] = audio[b * T + (T - 6) + tid];
        for (int idx = tid; idx < 64 * 4; idx += 256) {
            int c = idx >> 2, u = idx & 3;
            out[OFF_S2 + (b * 64 + c) * 4 + u] = c1s[(3 * 11 + 7 + u) * 64 + c];
        }
        for (int idx = tid; idx < 128 * 4; idx += 256) {
            int c = idx >> 2, u = idx & 3;
            out[OFF_S3 + (b * 128 + c) * 4 + u] = c2s[(3 * 7 + 3 + u) * 128 + c];
        }
        for (int idx = tid; idx < 256 * 2; idx += 256) {
            int c = idx >> 1, u = idx & 1;
            out[OFF_S4 + (b * 256 + c) * 2 + u] = c3s[(3 * 3 + 1 + u) * 256 + c];
        }
    }
}

// ---------------------------------------------------------------------------
// Kernel 2: RVQ (8 sequential codebooks, argmin over 1024 codes) + head GEMM.
// One block = one batch x 10 subsample positions. Codebook + head weight reads
// use transposed coalesced layouts.
// ---------------------------------------------------------------------------
#define RP 10
__global__ __launch_bounds__(256) void rvq_kernel(
    const float* __restrict__ cb,
    const float* __restrict__ hb,
    float* __restrict__ out)
{
    __shared__ float zblk[RP * DM];
    __shared__ float zqsh[RP * DM];
    __shared__ float rs[RP * 64];
    __shared__ unsigned long long cand[RP * 8];
    __shared__ unsigned long long bestk[RP];

    const int tid = threadIdx.x;
    const int lane = tid & 31;
    const int wid = tid >> 5;
    const int b = blockIdx.x / 30;
    const int g = blockIdx.x % 30;

    for (int idx = tid; idx < RP * DM; idx += 256) {
        int p = idx >> 9;
        zblk[idx] = g_z[(b * TS + g * RP + p) * DM + (idx & 511)];
    }
    __syncthreads();
    for (int idx = tid; idx < RP * 64; idx += 256) {
        int p = idx >> 6;
        rs[idx] = zblk[p * DM + (idx & 63)];
    }
    __syncthreads();

    for (int i = 0; i < NCB; i++) {
        const float* cbti = g_cbt + i * CBD * CBS;
        // each thread: codes tid, tid+256, tid+512, tid+768 vs all RP residuals
        float dot[4][RP];
        #pragma unroll
        for (int q = 0; q < 4; q++)
            #pragma unroll
            for (int p = 0; p < RP; p++) dot[q][p] = 0.f;
        for (int d = 0; d < CBD; d++) {
            float cv[4];
            #pragma unroll
            for (int q = 0; q < 4; q++) cv[q] = cbti[d * CBS + tid + q * 256];
            #pragma unroll
            for (int p = 0; p < RP; p++) {
                float rv = rs[p * 64 + d];
                #pragma unroll
                for (int q = 0; q < 4; q++) dot[q][p] = fmaf(cv[q], rv, dot[q][p]);
            }
        }
        // score = dot - 0.5|c|^2; argmax == argmin(dist); key packs (score, ~code)
        unsigned long long best[RP];
        #pragma unroll
        for (int p = 0; p < RP; p++) best[p] = 0ull;
        #pragma unroll
        for (int q = 0; q < 4; q++) {
            int code = tid + q * 256;
            float cn = g_cn[i * CBS + code];
            unsigned invc = ~(unsigned)code;
            #pragma unroll
            for (int p = 0; p < RP; p++) {
                float sc = dot[q][p] - cn;
                unsigned long long key = (((unsigned long long)fordu(sc)) << 32) | invc;
                if (key > best[p]) best[p] = key;
            }
        }
        #pragma unroll
        for (int off = 16; off > 0; off >>= 1) {
            #pragma unroll
            for (int p = 0; p < RP; p++) {
                unsigned long long other = __shfl_down_sync(0xFFFFFFFFu, best[p], off);
                if (other > best[p]) best[p] = other;
            }
        }
        if (lane == 0) {
            #pragma unroll
            for (int p = 0; p < RP; p++) cand[p * 8 + wid] = best[p];
        }
        __syncthreads();
        if (tid < RP) {
            unsigned long long m = cand[tid * 8];
            #pragma unroll
            for (int w = 1; w < 8; w++) {
                unsigned long long v = cand[tid * 8 + w];
                if (v > m) m = v;
            }
            bestk[tid] = m;
            unsigned code = ~(unsigned)(m & 0xFFFFFFFFull);
            out[OFF_A + (b * NCB + i) * TS + g * RP + tid] = (float)code;
        }
        __syncthreads();
        // write q into z_q, update residual r = z[i+1] + (r - q)
        for (int idx = tid; idx < RP * 64; idx += 256) {
            int p = idx >> 6, d = idx & 63;
            unsigned code = ~(unsigned)(bestk[p] & 0xFFFFFFFFull);
            float qv = cb[(i * CBS + code) * CBD + d];
            zqsh[p * DM + i * 64 + d] = qv;
            if (i < NCB - 1)
                rs[idx] = zblk[p * DM + (i + 1) * 64 + d] + rs[idx] - qv;
        }
        __syncthreads();
    }

    // head: b_logits[b,h,t,o] = z_q . head_w[h,o,:] + head_b[h,o]
    {
        float acc[RP];
        #pragma unroll
        for (int p = 0; p < RP; p++) acc[p] = 0.f;
        for (int d = 0; d < DM; d++) {
            float wv = g_hwt[d * 256 + tid];
            #pragma unroll
            for (int p = 0; p < RP; p++) acc[p] = fmaf(wv, zqsh[p * DM + d], acc[p]);
        }
        int h = tid >> 6, o = tid & 63;
        float bb = hb[tid];
        #pragma unroll
        for (int p = 0; p < RP; p++)
            out[OFF_BL + ((b * 4 + h) * TS + g * RP + p) * 64 + o] = acc[p] + bb;
    }
}

// ---------------------------------------------------------------------------
extern "C" void kernel_launch(void* const* d_in, const int* in_sizes, int n_in,
                              void* d_out, int out_size)
{
    const float* audio = (const float*)d_in[0];
    const float* w1 = (const float*)d_in[1];
    const float* b1 = (const float*)d_in[2];
    const float* w2 = (const float*)d_in[3];
    const float* b2 = (const float*)d_in[4];
    const float* w3 = (const float*)d_in[5];
    const float* b3 = (const float*)d_in[6];
    const float* w4 = (const float*)d_in[7];
    const float* b4 = (const float*)d_in[8];
    const float* cb = (const float*)d_in[9];
    const float* hw = (const float*)d_in[10];
    const float* hb = (const float*)d_in[11];
    float* out = (float*)d_out;

    prep_kernel<<<(N_PREP + 255) / 256, 256>>>(w2, w3, w4, hw, cb);
    enc_kernel<<<NB * 75, 256>>>(audio, w1, b1, b2, b3, b4, out);
    rvq_kernel<<<NB * 30, 256>>>(cb, hb, out);
}